// round 1
// baseline (speedup 1.0000x reference)
#include <cuda_runtime.h>
#include <math.h>

#define BB 16
#define TT 16
#define CCH 128
#define HW 1024
#define CHW (CCH*HW)          /* 131072 = 2^17 */
#define CAT (2*CCH*HW)        /* 262144 */

// ---------------- scratch (device globals; no allocations) ----------------
__device__ float g_Cst[BB*CHW];          // LSTM cell state
__device__ float g_m[BB*CHW];            // attention memory state
__device__ float g_cat[BB*CAT];          // [H ; x_t]  or  [H ; z]  (hz)
__device__ float g_zcat[BB*CAT];         // [zh ; zm]
__device__ float g_y4[BB*4*CHW];         // conv10..13 outputs
__device__ float g_att[BB*5*CHW];        // vh,kh,qh,km,vm   (reused for conv7..9 out)
__device__ float g_Wt5[5*128*128];       // W5 transposed -> [j][k][m]
__device__ float g_Wt8[8*256*128];       // W8 transposed -> [j][k][m]

__device__ __forceinline__ float sigmoidf_(float x){ return 1.f/(1.f+expf(-x)); }

// ---------------- one-time weight transpose (coalesced GEMM smem fills) ---
__global__ void k_transpose(const float* __restrict__ W5, const float* __restrict__ W8){
    int idx = blockIdx.x*blockDim.x + threadIdx.x;
    if (idx < 5*128*128){
        int j = idx/(128*128), r = idx%(128*128), o = r/128, i = r%128;
        g_Wt5[j*128*128 + i*128 + o] = W5[idx];
    }
    int i2 = idx - 5*128*128;
    if (i2 >= 0 && i2 < 8*128*256){
        int j = i2/(128*256), r = i2%(128*256), o = r/256, i = r%256;
        g_Wt8[j*256*128 + i*128 + o] = W8[i2];
    }
}

// ---------------- init: Cst=c0, m=0, cat = [H=0 ; x_0] ---------------------
__global__ void k_init(const float* __restrict__ c0, const float* __restrict__ x){
    int idx = blockIdx.x*blockDim.x + threadIdx.x;
    if (idx >= BB*CHW) return;
    int b = idx >> 17;
    int r = idx & (CHW-1);
    g_Cst[idx] = c0[idx];
    g_m[idx]   = 0.f;
    g_cat[(size_t)b*CAT + r]        = 0.f;
    g_cat[(size_t)b*CAT + CHW + r]  = x[(size_t)b*TT*CHW + r];  // t = 0
}

// ---------------- stacked 1x1-conv GEMM ------------------------------------
// Y[b, yChanOff + j*128 + m, n] = bias_j[m] + sum_k Wt_j[k][m] * X[b, k, n]
// X selected per stack index j (j < jSplit -> X0, else X1).
// Tile: M=128 (all out chans) x N=128 pixels, BK=16, 256 threads, 8x8 microtile.
__global__ __launch_bounds__(256)
void gemm_stacked(const float* __restrict__ Wt, const float* __restrict__ bias,
                  const float* __restrict__ X0, int x0Stride,
                  const float* __restrict__ X1, int x1Stride, int jSplit,
                  int K, float* __restrict__ Y, int yStride, int yChanOff)
{
    const int n0 = blockIdx.x * 128;
    const int j  = blockIdx.y;
    const int b  = blockIdx.z;
    const float* __restrict__ X = (j < jSplit) ? X0 + (size_t)b*x0Stride
                                               : X1 + (size_t)b*x1Stride;
    const float* __restrict__ Wj = Wt + (size_t)j*K*128;
    const float* __restrict__ bj = bias + j*128;

    __shared__ float Ws[16][128];
    __shared__ float Xs[16][128];

    const int tid  = threadIdx.x;
    const int tm   = tid >> 4;      // 0..15  (M groups of 8)
    const int tn   = tid & 15;      // 0..15  (N groups of 8)
    const int krow = tid >> 5;      // 0..7
    const int nq   = tid & 31;      // 0..31

    float acc[8][8] = {};

    for (int kk = 0; kk < K; kk += 16){
        #pragma unroll
        for (int r = 0; r < 2; r++){
            int k = kk + krow + r*8;
            float4 wv = *(const float4*)(Wj + (size_t)k*128 + nq*4);
            *(float4*)&Ws[krow + r*8][nq*4] = wv;
            float4 xv = *(const float4*)(X + (size_t)k*HW + n0 + nq*4);
            *(float4*)&Xs[krow + r*8][nq*4] = xv;
        }
        __syncthreads();
        #pragma unroll
        for (int k = 0; k < 16; k++){
            float wf[8], xf[8];
            *(float4*)&wf[0] = *(const float4*)&Ws[k][tm*8];
            *(float4*)&wf[4] = *(const float4*)&Ws[k][tm*8+4];
            *(float4*)&xf[0] = *(const float4*)&Xs[k][tn*8];
            *(float4*)&xf[4] = *(const float4*)&Xs[k][tn*8+4];
            #pragma unroll
            for (int i = 0; i < 8; i++)
                #pragma unroll
                for (int q = 0; q < 8; q++)
                    acc[i][q] += wf[i]*xf[q];
        }
        __syncthreads();
    }

    #pragma unroll
    for (int i = 0; i < 8; i++){
        int m = tm*8 + i;
        float bv = bj[m];
        float* out = Y + (size_t)b*yStride + (size_t)(yChanOff + j*CCH + m)*HW + n0 + tn*8;
        float4 o0 = {acc[i][0]+bv, acc[i][1]+bv, acc[i][2]+bv, acc[i][3]+bv};
        float4 o1 = {acc[i][4]+bv, acc[i][5]+bv, acc[i][6]+bv, acc[i][7]+bv};
        *(float4*)out     = o0;
        *(float4*)(out+4) = o1;
    }
}

// ---------------- LSTM gate update (after conv10..13) ----------------------
__global__ void k_lstm(){
    int idx = blockIdx.x*blockDim.x + threadIdx.x;
    if (idx >= BB*CHW) return;
    int b = idx >> 17;
    int r = idx & (CHW-1);
    const float* y = g_y4 + (size_t)b*4*CHW;
    float a  = sigmoidf_(y[r]);             // conv10
    float ga = sigmoidf_(y[CHW   + r]);     // conv11
    float gv = tanhf   (y[2*CHW + r]);      // conv12
    float cs = g_Cst[idx]*a + ga*gv;
    float a1 = sigmoidf_(y[3*CHW + r]);     // conv13
    float h  = a1 * tanhf(cs);
    g_Cst[idx] = cs;
    g_cat[(size_t)b*CAT + r] = h;           // H half of cat
}

// ---------------- attention: transposed q + two row-softmaxes --------------
// One block per (b,c); warp h handles spatial row h, lane = w.
__global__ __launch_bounds__(1024) void k_attn(){
    const int b = blockIdx.x >> 7;
    const int c = blockIdx.x & 127;
    const float* base = g_att + (size_t)b*5*CHW + (size_t)c*HW;
    const float* vh = base;                 // conv1
    const float* kh = base + CHW;           // conv2
    const float* qh = base + 2*CHW;         // conv3 (pre-transpose)
    const float* km = base + 3*CHW;         // conv4
    const float* vm = base + 4*CHW;         // conv5

    __shared__ float qs[32][33];
    const int tid = threadIdx.x;
    const int h = tid >> 5, w = tid & 31;
    qs[h][w] = qh[tid];
    __syncthreads();
    float q = qs[w][h];                     // qh[b,c,w,h] = transposed q

    // ah = softmax_w(kh*q); zh = vh*ah
    float s1 = kh[tid] * q;
    float mx = s1;
    #pragma unroll
    for (int o = 16; o; o >>= 1) mx = fmaxf(mx, __shfl_xor_sync(0xffffffffu, mx, o));
    float e1 = expf(s1 - mx);
    float sm = e1;
    #pragma unroll
    for (int o = 16; o; o >>= 1) sm += __shfl_xor_sync(0xffffffffu, sm, o);
    float zh = vh[tid] * (e1 / sm);

    // am = softmax_w(q*km); zm = vm*am
    float s2 = q * km[tid];
    float mx2 = s2;
    #pragma unroll
    for (int o = 16; o; o >>= 1) mx2 = fmaxf(mx2, __shfl_xor_sync(0xffffffffu, mx2, o));
    float e2 = expf(s2 - mx2);
    float sm2 = e2;
    #pragma unroll
    for (int o = 16; o; o >>= 1) sm2 += __shfl_xor_sync(0xffffffffu, sm2, o);
    float zm = vm[tid] * (e2 / sm2);

    size_t zb = (size_t)b*CAT + (size_t)c*HW + tid;
    g_zcat[zb]       = zh;
    g_zcat[zb + CHW] = zm;
}

// ---------------- final gates (after conv7..9), state update ---------------
__global__ void k_final(const float* __restrict__ x, float* __restrict__ out, int t){
    int idx = blockIdx.x*blockDim.x + threadIdx.x;
    if (idx >= BB*CHW) return;
    int b = idx >> 17;
    int r = idx & (CHW-1);
    const float* y = g_att + (size_t)b*3*CHW;   // conv7,8,9 outputs (stride 3*CHW)
    float ot = sigmoidf_(y[r]);
    float gt = tanhf   (y[CHW   + r]);
    float it = sigmoidf_(y[2*CHW + r]);
    float mo = g_m[idx];
    float mt = gt*it + (1.f - it)*mo;
    float ht = ot * mt;
    g_m[idx] = mt;
    g_cat[(size_t)b*CAT + r] = ht;              // new H
    if (t == TT-1){
        out[idx] = ht;
    } else {
        g_cat[(size_t)b*CAT + CHW + r] = x[(size_t)b*TT*CHW + (size_t)(t+1)*CHW + r];
    }
}

// ---------------- launcher --------------------------------------------------
extern "C" void kernel_launch(void* const* d_in, const int* in_sizes, int n_in,
                              void* d_out, int out_size)
{
    const float* x  = (const float*)d_in[0];
    const float* c0 = (const float*)d_in[1];
    const float* W5 = (const float*)d_in[2];
    const float* b5 = (const float*)d_in[3];
    const float* W8 = (const float*)d_in[4];
    const float* b8 = (const float*)d_in[5];
    float* out = (float*)d_out;

    float *pcat, *pzcat, *py4, *patt, *pm, *pWt5, *pWt8;
    cudaGetSymbolAddress((void**)&pcat,  g_cat);
    cudaGetSymbolAddress((void**)&pzcat, g_zcat);
    cudaGetSymbolAddress((void**)&py4,   g_y4);
    cudaGetSymbolAddress((void**)&patt,  g_att);
    cudaGetSymbolAddress((void**)&pm,    g_m);
    cudaGetSymbolAddress((void**)&pWt5,  g_Wt5);
    cudaGetSymbolAddress((void**)&pWt8,  g_Wt8);

    k_transpose<<<(5*128*128 + 8*128*256 + 255)/256, 256>>>(W5, W8);
    k_init<<<(BB*CHW + 255)/256, 256>>>(c0, x);

    for (int t = 0; t < TT; t++){
        // conv10..13 on [H ; x_t]  (W8[4..7], K=256)
        gemm_stacked<<<dim3(8,4,BB),256>>>(pWt8 + (size_t)4*256*128, b8 + 4*128,
                                           pcat, CAT, pcat, CAT, 4,
                                           256, py4, 4*CHW, 0);
        k_lstm<<<(BB*CHW + 255)/256, 256>>>();
        // conv1..3 on H (K=128), conv4..5 on m (K=128)
        gemm_stacked<<<dim3(8,5,BB),256>>>(pWt5, b5,
                                           pcat, CAT, pm, CHW, 3,
                                           128, patt, 5*CHW, 0);
        k_attn<<<BB*CCH, 1024>>>();
        // conv6 on [zh ; zm] -> z into cat's second half (K=256)
        gemm_stacked<<<dim3(8,1,BB),256>>>(pWt8, b8,
                                           pzcat, CAT, pzcat, CAT, 1,
                                           256, pcat, CAT, CCH);
        // conv7..9 on hz = [H ; z] (K=256)
        gemm_stacked<<<dim3(8,3,BB),256>>>(pWt8 + (size_t)1*256*128, b8 + 128,
                                           pcat, CAT, pcat, CAT, 3,
                                           256, patt, 3*CHW, 0);
        k_final<<<(BB*CHW + 255)/256, 256>>>(x, out, t);
    }
}

// round 2
// speedup vs baseline: 1.0008x; 1.0008x over previous
#include <cuda_runtime.h>
#include <math.h>

#define BB 16
#define TT 16
#define CCH 128
#define HW 1024
#define CHW (CCH*HW)          /* 131072 = 2^17 */
#define CAT (2*CCH*HW)        /* 262144 */

// ---------------- scratch (device globals; no allocations) ----------------
__device__ float g_Cst[BB*CHW];          // LSTM cell state
__device__ float g_m[BB*CHW];            // attention memory state
__device__ float g_cat[BB*CAT];          // [H ; x_t]  or  [H ; z]  (hz)
__device__ float g_zcat[BB*CAT];         // [zh ; zm]
__device__ float g_y4[BB*4*CHW];         // conv10..13 outputs
__device__ float g_att[BB*5*CHW];        // vh,kh,qh,km,vm   (reused for conv7..9 out)
__device__ float g_Wt5[5*128*128];       // W5 transposed -> [j][k][m]
__device__ float g_Wt8[8*256*128];       // W8 transposed -> [j][k][m]

__device__ __forceinline__ float sigmoidf_(float x){ return 1.f/(1.f+expf(-x)); }

// ---------------- one-time weight transpose (coalesced GEMM smem fills) ---
__global__ void k_transpose(const float* __restrict__ W5, const float* __restrict__ W8){
    int idx = blockIdx.x*blockDim.x + threadIdx.x;
    if (idx < 5*128*128){
        int j = idx/(128*128), r = idx%(128*128), o = r/128, i = r%128;
        g_Wt5[j*128*128 + i*128 + o] = W5[idx];
    }
    int i2 = idx - 5*128*128;
    if (i2 >= 0 && i2 < 8*128*256){
        int j = i2/(128*256), r = i2%(128*256), o = r/256, i = r%256;
        g_Wt8[j*256*128 + i*128 + o] = W8[i2];
    }
}

// ---------------- init: Cst=c0, m=0, cat = [H=0 ; x_0] ---------------------
__global__ void k_init(const float* __restrict__ c0, const float* __restrict__ x){
    int idx = blockIdx.x*blockDim.x + threadIdx.x;
    if (idx >= BB*CHW) return;
    int b = idx >> 17;
    int r = idx & (CHW-1);
    g_Cst[idx] = c0[idx];
    g_m[idx]   = 0.f;
    g_cat[(size_t)b*CAT + r]        = 0.f;
    g_cat[(size_t)b*CAT + CHW + r]  = x[(size_t)b*TT*CHW + r];  // t = 0
}

// ---------------- stacked 1x1-conv GEMM ------------------------------------
// Y[b, yChanOff + j*128 + m, n] = bias_j[m] + sum_k Wt_j[k][m] * X[b, k, n]
// X selected per stack index j (j < jSplit -> X0, else X1).
// Tile: M=128 (all out chans) x N=128 pixels, BK=16, 256 threads, 8x8 microtile.
__global__ __launch_bounds__(256)
void gemm_stacked(const float* __restrict__ Wt, const float* __restrict__ bias,
                  const float* __restrict__ X0, int x0Stride,
                  const float* __restrict__ X1, int x1Stride, int jSplit,
                  int K, float* __restrict__ Y, int yStride, int yChanOff)
{
    const int n0 = blockIdx.x * 128;
    const int j  = blockIdx.y;
    const int b  = blockIdx.z;
    const float* __restrict__ X = (j < jSplit) ? X0 + (size_t)b*x0Stride
                                               : X1 + (size_t)b*x1Stride;
    const float* __restrict__ Wj = Wt + (size_t)j*K*128;
    const float* __restrict__ bj = bias + j*128;

    __shared__ float Ws[16][128];
    __shared__ float Xs[16][128];

    const int tid  = threadIdx.x;
    const int tm   = tid >> 4;      // 0..15  (M groups of 8)
    const int tn   = tid & 15;      // 0..15  (N groups of 8)
    const int krow = tid >> 5;      // 0..7
    const int nq   = tid & 31;      // 0..31

    float acc[8][8] = {};

    for (int kk = 0; kk < K; kk += 16){
        #pragma unroll
        for (int r = 0; r < 2; r++){
            int k = kk + krow + r*8;
            float4 wv = *(const float4*)(Wj + (size_t)k*128 + nq*4);
            *(float4*)&Ws[krow + r*8][nq*4] = wv;
            float4 xv = *(const float4*)(X + (size_t)k*HW + n0 + nq*4);
            *(float4*)&Xs[krow + r*8][nq*4] = xv;
        }
        __syncthreads();
        #pragma unroll
        for (int k = 0; k < 16; k++){
            float wf[8], xf[8];
            *(float4*)&wf[0] = *(const float4*)&Ws[k][tm*8];
            *(float4*)&wf[4] = *(const float4*)&Ws[k][tm*8+4];
            *(float4*)&xf[0] = *(const float4*)&Xs[k][tn*8];
            *(float4*)&xf[4] = *(const float4*)&Xs[k][tn*8+4];
            #pragma unroll
            for (int i = 0; i < 8; i++)
                #pragma unroll
                for (int q = 0; q < 8; q++)
                    acc[i][q] += wf[i]*xf[q];
        }
        __syncthreads();
    }

    #pragma unroll
    for (int i = 0; i < 8; i++){
        int m = tm*8 + i;
        float bv = bj[m];
        float* out = Y + (size_t)b*yStride + (size_t)(yChanOff + j*CCH + m)*HW + n0 + tn*8;
        float4 o0 = {acc[i][0]+bv, acc[i][1]+bv, acc[i][2]+bv, acc[i][3]+bv};
        float4 o1 = {acc[i][4]+bv, acc[i][5]+bv, acc[i][6]+bv, acc[i][7]+bv};
        *(float4*)out     = o0;
        *(float4*)(out+4) = o1;
    }
}

// ---------------- LSTM gate update (after conv10..13) ----------------------
__global__ void k_lstm(){
    int idx = blockIdx.x*blockDim.x + threadIdx.x;
    if (idx >= BB*CHW) return;
    int b = idx >> 17;
    int r = idx & (CHW-1);
    const float* y = g_y4 + (size_t)b*4*CHW;
    float a  = sigmoidf_(y[r]);             // conv10
    float ga = sigmoidf_(y[CHW   + r]);     // conv11
    float gv = tanhf   (y[2*CHW + r]);      // conv12
    float cs = g_Cst[idx]*a + ga*gv;
    float a1 = sigmoidf_(y[3*CHW + r]);     // conv13
    float h  = a1 * tanhf(cs);
    g_Cst[idx] = cs;
    g_cat[(size_t)b*CAT + r] = h;           // H half of cat
}

// ---------------- attention: transposed q + two row-softmaxes --------------
// One block per (b,c); warp h handles spatial row h, lane = w.
__global__ __launch_bounds__(1024) void k_attn(){
    const int b = blockIdx.x >> 7;
    const int c = blockIdx.x & 127;
    const float* base = g_att + (size_t)b*5*CHW + (size_t)c*HW;
    const float* vh = base;                 // conv1
    const float* kh = base + CHW;           // conv2
    const float* qh = base + 2*CHW;         // conv3 (pre-transpose)
    const float* km = base + 3*CHW;         // conv4
    const float* vm = base + 4*CHW;         // conv5

    __shared__ float qs[32][33];
    const int tid = threadIdx.x;
    const int h = tid >> 5, w = tid & 31;
    qs[h][w] = qh[tid];
    __syncthreads();
    float q = qs[w][h];                     // qh[b,c,w,h] = transposed q

    // ah = softmax_w(kh*q); zh = vh*ah
    float s1 = kh[tid] * q;
    float mx = s1;
    #pragma unroll
    for (int o = 16; o; o >>= 1) mx = fmaxf(mx, __shfl_xor_sync(0xffffffffu, mx, o));
    float e1 = expf(s1 - mx);
    float sm = e1;
    #pragma unroll
    for (int o = 16; o; o >>= 1) sm += __shfl_xor_sync(0xffffffffu, sm, o);
    float zh = vh[tid] * (e1 / sm);

    // am = softmax_w(q*km); zm = vm*am
    float s2 = q * km[tid];
    float mx2 = s2;
    #pragma unroll
    for (int o = 16; o; o >>= 1) mx2 = fmaxf(mx2, __shfl_xor_sync(0xffffffffu, mx2, o));
    float e2 = expf(s2 - mx2);
    float sm2 = e2;
    #pragma unroll
    for (int o = 16; o; o >>= 1) sm2 += __shfl_xor_sync(0xffffffffu, sm2, o);
    float zm = vm[tid] * (e2 / sm2);

    size_t zb = (size_t)b*CAT + (size_t)c*HW + tid;
    g_zcat[zb]       = zh;
    g_zcat[zb + CHW] = zm;
}

// ---------------- final gates (after conv7..9), state update ---------------
__global__ void k_final(const float* __restrict__ x, float* __restrict__ out, int t){
    int idx = blockIdx.x*blockDim.x + threadIdx.x;
    if (idx >= BB*CHW) return;
    int b = idx >> 17;
    int r = idx & (CHW-1);
    const float* y = g_att + (size_t)b*3*CHW;   // conv7,8,9 outputs (stride 3*CHW)
    float ot = sigmoidf_(y[r]);
    float gt = tanhf   (y[CHW   + r]);
    float it = sigmoidf_(y[2*CHW + r]);
    float mo = g_m[idx];
    float mt = gt*it + (1.f - it)*mo;
    float ht = ot * mt;
    g_m[idx] = mt;
    g_cat[(size_t)b*CAT + r] = ht;              // new H
    if (t == TT-1){
        out[idx] = ht;
    } else {
        g_cat[(size_t)b*CAT + CHW + r] = x[(size_t)b*TT*CHW + (size_t)(t+1)*CHW + r];
    }
}

// ---------------- launcher --------------------------------------------------
extern "C" void kernel_launch(void* const* d_in, const int* in_sizes, int n_in,
                              void* d_out, int out_size)
{
    const float* x  = (const float*)d_in[0];
    const float* c0 = (const float*)d_in[1];
    const float* W5 = (const float*)d_in[2];
    const float* b5 = (const float*)d_in[3];
    const float* W8 = (const float*)d_in[4];
    const float* b8 = (const float*)d_in[5];
    float* out = (float*)d_out;

    float *pcat, *pzcat, *py4, *patt, *pm, *pWt5, *pWt8;
    cudaGetSymbolAddress((void**)&pcat,  g_cat);
    cudaGetSymbolAddress((void**)&pzcat, g_zcat);
    cudaGetSymbolAddress((void**)&py4,   g_y4);
    cudaGetSymbolAddress((void**)&patt,  g_att);
    cudaGetSymbolAddress((void**)&pm,    g_m);
    cudaGetSymbolAddress((void**)&pWt5,  g_Wt5);
    cudaGetSymbolAddress((void**)&pWt8,  g_Wt8);

    k_transpose<<<(5*128*128 + 8*128*256 + 255)/256, 256>>>(W5, W8);
    k_init<<<(BB*CHW + 255)/256, 256>>>(c0, x);

    for (int t = 0; t < TT; t++){
        // conv10..13 on [H ; x_t]  (W8[4..7], K=256)
        gemm_stacked<<<dim3(8,4,BB),256>>>(pWt8 + (size_t)4*256*128, b8 + 4*128,
                                           pcat, CAT, pcat, CAT, 4,
                                           256, py4, 4*CHW, 0);
        k_lstm<<<(BB*CHW + 255)/256, 256>>>();
        // conv1..3 on H (K=128), conv4..5 on m (K=128)
        gemm_stacked<<<dim3(8,5,BB),256>>>(pWt5, b5,
                                           pcat, CAT, pm, CHW, 3,
                                           128, patt, 5*CHW, 0);
        k_attn<<<BB*CCH, 1024>>>();
        // conv6 on [zh ; zm] -> z into cat's second half (K=256)
        gemm_stacked<<<dim3(8,1,BB),256>>>(pWt8, b8,
                                           pzcat, CAT, pzcat, CAT, 1,
                                           256, pcat, CAT, CCH);
        // conv7..9 on hz = [H ; z] (K=256)
        gemm_stacked<<<dim3(8,3,BB),256>>>(pWt8 + (size_t)1*256*128, b8 + 128,
                                           pcat, CAT, pcat, CAT, 3,
                                           256, patt, 3*CHW, 0);
        k_final<<<(BB*CHW + 255)/256, 256>>>(x, out, t);
    }
}

// round 6
// speedup vs baseline: 1.2909x; 1.2899x over previous
#include <cuda_runtime.h>
#include <cuda_fp16.h>
#include <math.h>
#include <stdint.h>

#define NPIX 16384
#define TT 16

// ---------------- device scratch (pixel-major [NPIX][ch]) ------------------
__device__ float g_H [NPIX*128];
__device__ float g_m [NPIX*128];
__device__ float g_C [NPIX*128];
__device__ float g_z [NPIX*128];
__device__ float g_zh[NPIX*128];
__device__ float g_zm[NPIX*128];
__device__ float g_Y [NPIX*640];                // vh|kh|qh|km|vm
__device__ float g_y4[NPIX*512];                // conv10..13 raw
__device__ float g_g3[NPIX*384];                // conv7..9 raw
__device__ float g_xT[(size_t)TT*NPIX*128];
__device__ __half g_W5h[5*128*128], g_W5l[5*128*128];   // [j][k][o] k-major
__device__ __half g_W8h[8*256*128], g_W8l[8*256*128];

__device__ __forceinline__ float sigmoidf_(float x){ return 1.f/(1.f+expf(-x)); }
__device__ __forceinline__ uint32_t smem_u32(const void* p){
    uint32_t a; asm("{ .reg .u64 t; cvta.to.shared.u64 t, %1; cvt.u32.u64 %0, t; }":"=r"(a):"l"(p)); return a;
}

#define LDSM4(r, a) asm volatile("ldmatrix.sync.aligned.m8n8.x4.shared.b16 {%0,%1,%2,%3}, [%4];" \
  : "=r"((r)[0]),"=r"((r)[1]),"=r"((r)[2]),"=r"((r)[3]) : "r"(a))
#define LDSM4T(r, a) asm volatile("ldmatrix.sync.aligned.m8n8.x4.trans.shared.b16 {%0,%1,%2,%3}, [%4];" \
  : "=r"((r)[0]),"=r"((r)[1]),"=r"((r)[2]),"=r"((r)[3]) : "r"(a))
#define MMA(d, a, b0_, b1_) asm volatile( \
  "mma.sync.aligned.m16n8k16.row.col.f32.f16.f16.f32 {%0,%1,%2,%3},{%4,%5,%6,%7},{%8,%9},{%0,%1,%2,%3};" \
  : "+f"((d)[0]),"+f"((d)[1]),"+f"((d)[2]),"+f"((d)[3]) \
  : "r"((a)[0]),"r"((a)[1]),"r"((a)[2]),"r"((a)[3]), "r"(b0_),"r"(b1_))

// smem map (bytes). A: [128][KP<=264] halves hi+lo; B: [64][136] halves hi+lo.
#define KPMAX 264
#define A_LO_OFF (128*KPMAX*2)              /* 67584 */
#define B_HI_OFF (2*128*KPMAX*2)            /* 135168 */
#define B_LO_OFF (B_HI_OFF + 64*136*2)      /* +17408 */
#define SMEM_G   (B_HI_OFF + 2*64*136*2)    /* 169984 */

// ---------------- weight prep: fp32 -> k-major fp16 hi/lo ------------------
__global__ void k_wprep(const float* __restrict__ W5, const float* __restrict__ W8){
    int idx = blockIdx.x*blockDim.x + threadIdx.x;
    if (idx < 5*128*128){
        int j = idx/(128*128), r = idx%(128*128), o = r/128, k = r%128;
        float v = W5[idx];
        __half h = __float2half_rn(v);
        __half l = __float2half_rn(v - __half2float(h));
        g_W5h[(j*128 + k)*128 + o] = h;
        g_W5l[(j*128 + k)*128 + o] = l;
        return;
    }
    int i2 = idx - 5*128*128;
    if (i2 >= 0 && i2 < 8*128*256){
        int j = i2/(128*256), r = i2%(128*256), o = r/256, k = r%256;
        float v = W8[i2];
        __half h = __float2half_rn(v);
        __half l = __float2half_rn(v - __half2float(h));
        g_W8h[((size_t)j*256 + k)*128 + o] = h;
        g_W8l[((size_t)j*256 + k)*128 + o] = l;
    }
}

// ---------------------------------------------------------------------------
// GEMM: out[p][coloff + j*128 + c] = bias[j*128+c] + sum_k A[p][k]*W[j][c][k]
// A fp32 pixel-major from A0 (cols < kbSplit*64) / A1 (rest). fp16 hi/lo x3.
// ---------------------------------------------------------------------------
__global__ __launch_bounds__(256)
void gemm_mma(const float* __restrict__ A0, const float* __restrict__ A1, int kbSplit,
              int KB, const __half* __restrict__ Wh, const __half* __restrict__ Wl,
              const float* __restrict__ bias, int NJ,
              float* __restrict__ out, int outStride, int outColOff)
{
    extern __shared__ char smem[];
    half* sAh = (half*)(smem);
    half* sAl = (half*)(smem + A_LO_OFF);
    half* sBh = (half*)(smem + B_HI_OFF);
    half* sBl = (half*)(smem + B_LO_OFF);
    const int tid = threadIdx.x, wid = tid>>5, lane = tid&31;
    const int p0 = blockIdx.x*128;
    const int K = KB*64, KP = K + 8;

    // ---- stage A hi/lo once
    const int nf4 = K >> 2;
    for (int q = tid; q < 128*nf4; q += 256){
        int r = q / nf4, c = (q - r*nf4)*4;
        const float* src = (c < kbSplit*64) ? A0 + (size_t)(p0+r)*128 + c
                                            : A1 + (size_t)(p0+r)*128 + (c - kbSplit*64);
        float4 v = *(const float4*)src;
        __half2 h01 = __floats2half2_rn(v.x, v.y);
        __half2 h23 = __floats2half2_rn(v.z, v.w);
        __half2 l01 = __floats2half2_rn(v.x - __low2float(h01), v.y - __high2float(h01));
        __half2 l23 = __floats2half2_rn(v.z - __low2float(h23), v.w - __high2float(h23));
        int o = r*KP + c;
        *(__half2*)(sAh + o) = h01; *(__half2*)(sAh + o + 2) = h23;
        *(__half2*)(sAl + o) = l01; *(__half2*)(sAl + o + 2) = l23;
    }

    const int wm = wid >> 2, wn = wid & 3;         // warp tile: 64(M) x 32(N)
    const int m0 = wm*64, n0 = wn*32;
    const int l15 = lane & 15, lH = (lane >> 4) << 3;
    const uint32_t sbase = smem_u32(smem);

    for (int j = 0; j < NJ; j++){
        float d[4][4][4];
        #pragma unroll
        for (int a=0;a<4;a++){ 
            #pragma unroll
            for(int b=0;b<4;b++){ 
                #pragma unroll
                for(int e=0;e<4;e++) d[a][b][e]=0.f; } }

        for (int kc = 0; kc < KB; kc++){
            __syncthreads();
            const __half* srcH = Wh + ((size_t)j*K + kc*64)*128;
            const __half* srcL = Wl + ((size_t)j*K + kc*64)*128;
            for (int q = tid; q < 1024; q += 256){
                int r = q >> 4, s8 = (q & 15) << 3;
                *(uint4*)(sBh + r*136 + s8) = *(const uint4*)(srcH + (size_t)r*128 + s8);
                *(uint4*)(sBl + r*136 + s8) = *(const uint4*)(srcL + (size_t)r*128 + s8);
            }
            __syncthreads();
            #pragma unroll
            for (int ks = 0; ks < 4; ks++){
                const int k = ks*16;
                uint32_t AH[4][4], AL[4][4], BH[2][4], BL[2][4];
                #pragma unroll
                for (int mi = 0; mi < 4; mi++){
                    uint32_t ad = sbase + ((uint32_t)(m0 + mi*16 + l15)*KP + kc*64 + k + lH)*2;
                    LDSM4(AH[mi], ad);
                    LDSM4(AL[mi], ad + A_LO_OFF);
                }
                #pragma unroll
                for (int bt = 0; bt < 2; bt++){
                    uint32_t bd = sbase + B_HI_OFF + ((uint32_t)(k + l15)*136 + n0 + bt*16 + lH)*2;
                    LDSM4T(BH[bt], bd);
                    LDSM4T(BL[bt], bd + (B_LO_OFF - B_HI_OFF));
                }
                #pragma unroll
                for (int mi = 0; mi < 4; mi++){
                    #pragma unroll
                    for (int nj = 0; nj < 4; nj++){
                        const int t = nj >> 1, o = (nj & 1)*2;
                        MMA(d[mi][nj], AH[mi], BH[t][o], BH[t][o+1]);
                        MMA(d[mi][nj], AL[mi], BH[t][o], BH[t][o+1]);
                        MMA(d[mi][nj], AH[mi], BL[t][o], BL[t][o+1]);
                    }
                }
            }
        }
        // ---- epilogue: frags -> smem (reuse B region) -> coalesced gmem
        float* sbuf = (float*)(smem + B_HI_OFF);
        #pragma unroll
        for (int h2 = 0; h2 < 2; h2++){
            __syncthreads();
            if (wm == h2){
                #pragma unroll
                for (int mi = 0; mi < 4; mi++){
                    int r0 = mi*16 + (lane>>2);
                    #pragma unroll
                    for (int nj = 0; nj < 4; nj++){
                        int c = n0 + nj*8 + ((lane&3)<<1);
                        sbuf[r0*132 + c]       = d[mi][nj][0];
                        sbuf[r0*132 + c + 1]   = d[mi][nj][1];
                        sbuf[(r0+8)*132 + c]   = d[mi][nj][2];
                        sbuf[(r0+8)*132 + c+1] = d[mi][nj][3];
                    }
                }
            }
            __syncthreads();
            for (int q = tid; q < 64*32; q += 256){
                int r = q >> 5, c4 = (q & 31) << 2;
                float4 v = *(float4*)&sbuf[r*132 + c4];
                float4 bv = *(const float4*)&bias[j*128 + c4];
                v.x += bv.x; v.y += bv.y; v.z += bv.z; v.w += bv.w;
                *(float4*)(out + (size_t)(p0 + h2*64 + r)*outStride + outColOff + j*128 + c4) = v;
            }
        }
    }
}

// ---------------- LSTM gates (after conv10..13) ----------------------------
__global__ void k_lstm(){
    int idx = blockIdx.x*blockDim.x + threadIdx.x;   // 2M
    int p = idx >> 7, c = idx & 127;
    const float* y = g_y4 + (size_t)p*512;
    float a  = sigmoidf_(y[c]);
    float ga = sigmoidf_(y[128 + c]);
    float gv = tanhf   (y[256 + c]);
    float a1 = sigmoidf_(y[384 + c]);
    float cs = g_C[idx]*a + ga*gv;
    g_C[idx] = cs;
    g_H[idx] = a1 * tanhf(cs);
}

// ---------------- final gates (after conv7..9) -----------------------------
__global__ void k_final(){
    int idx = blockIdx.x*blockDim.x + threadIdx.x;
    int p = idx >> 7, c = idx & 127;
    const float* y = g_g3 + (size_t)p*384;
    float ot = sigmoidf_(y[c]);
    float gt = tanhf   (y[128 + c]);
    float it = sigmoidf_(y[256 + c]);
    float mt = gt*it + (1.f - it)*g_m[idx];
    g_m[idx] = mt;
    g_H[idx] = ot * mt;
}

// ---------------- attention -------------------------------------------------
#define AT_P 132
#define SMEM_ATTN (5*32*AT_P*4)
__global__ __launch_bounds__(256) void k_attn(){
    extern __shared__ float s[];
    float* s_vh = s;
    float* s_kh = s + 1*32*AT_P;
    float* s_qt = s + 2*32*AT_P;
    float* s_km = s + 3*32*AT_P;
    float* s_vm = s + 4*32*AT_P;
    const int tid = threadIdx.x;
    const int b = blockIdx.x >> 5, h = blockIdx.x & 31;
    const int r0 = b*1024 + h*32;

    for (int q = tid; q < 32*32; q += 256){
        int w = q >> 5, c4 = (q & 31) * 4;
        const float* row = g_Y + (size_t)(r0 + w)*640;
        float4 v;
        v = *(const float4*)(row +   0 + c4); *(float4*)&s_vh[w*AT_P+c4] = v;
        v = *(const float4*)(row + 128 + c4); *(float4*)&s_kh[w*AT_P+c4] = v;
        v = *(const float4*)(row + 384 + c4); *(float4*)&s_km[w*AT_P+c4] = v;
        v = *(const float4*)(row + 512 + c4); *(float4*)&s_vm[w*AT_P+c4] = v;
        const float* qrow = g_Y + (size_t)(b*1024 + w*32 + h)*640 + 256;   // transposed q
        v = *(const float4*)(qrow + c4);      *(float4*)&s_qt[w*AT_P+c4] = v;
    }
    __syncthreads();

    const int wid = tid >> 5, lane = tid & 31;           // lane = w
    for (int i = 0; i < 16; i++){
        int c = wid + 8*i;
        float qv = s_qt[lane*AT_P + c];
        float s1 = s_kh[lane*AT_P + c] * qv;
        float mx = s1;
        #pragma unroll
        for (int o = 16; o; o >>= 1) mx = fmaxf(mx, __shfl_xor_sync(0xffffffffu, mx, o));
        float e1 = expf(s1 - mx), sm = e1;
        #pragma unroll
        for (int o = 16; o; o >>= 1) sm += __shfl_xor_sync(0xffffffffu, sm, o);
        s_vh[lane*AT_P + c] *= (e1 / sm);                // zh
        float s2 = qv * s_km[lane*AT_P + c];
        float mx2 = s2;
        #pragma unroll
        for (int o = 16; o; o >>= 1) mx2 = fmaxf(mx2, __shfl_xor_sync(0xffffffffu, mx2, o));
        float e2 = expf(s2 - mx2), sm2 = e2;
        #pragma unroll
        for (int o = 16; o; o >>= 1) sm2 += __shfl_xor_sync(0xffffffffu, sm2, o);
        s_vm[lane*AT_P + c] *= (e2 / sm2);               // zm
    }
    __syncthreads();
    for (int q = tid; q < 32*32; q += 256){
        int w = q >> 5, c4 = (q & 31) * 4;
        *(float4*)(g_zh + (size_t)(r0 + w)*128 + c4) = *(float4*)&s_vh[w*AT_P + c4];
        *(float4*)(g_zm + (size_t)(r0 + w)*128 + c4) = *(float4*)&s_vm[w*AT_P + c4];
    }
}

// ---------------- layout transposes ----------------------------------------
#define SMEM_TR (128*132*4)
__global__ __launch_bounds__(256) void k_xT(const float* __restrict__ x){
    extern __shared__ float s[];
    int bid = blockIdx.x;
    int b = bid >> 7, t = (bid >> 3) & 15, n0 = (bid & 7) * 128;
    const float* src = x + (size_t)(b*16 + t)*128*1024;
    for (int q = threadIdx.x; q < 128*32; q += 256){
        int c = q >> 5, n4 = (q & 31) * 4;
        float4 v = *(const float4*)(src + (size_t)c*1024 + n0 + n4);
        s[(n4+0)*132 + c] = v.x; s[(n4+1)*132 + c] = v.y;
        s[(n4+2)*132 + c] = v.z; s[(n4+3)*132 + c] = v.w;
    }
    __syncthreads();
    float* dst = g_xT + ((size_t)t*NPIX + b*1024 + n0)*128;
    for (int q = threadIdx.x; q < 128*32; q += 256){
        int n = q >> 5, c4 = (q & 31) * 4;
        *(float4*)(dst + (size_t)n*128 + c4) = *(float4*)&s[n*132 + c4];
    }
}
__global__ __launch_bounds__(256) void k_init(const float* __restrict__ c0){
    extern __shared__ float s[];
    int b = blockIdx.x >> 3, n0 = (blockIdx.x & 7) * 128;
    const float* src = c0 + (size_t)b*128*1024;
    for (int q = threadIdx.x; q < 128*32; q += 256){
        int c = q >> 5, n4 = (q & 31) * 4;
        float4 v = *(const float4*)(src + (size_t)c*1024 + n0 + n4);
        s[(n4+0)*132 + c] = v.x; s[(n4+1)*132 + c] = v.y;
        s[(n4+2)*132 + c] = v.z; s[(n4+3)*132 + c] = v.w;
    }
    __syncthreads();
    size_t base = (size_t)(b*1024 + n0)*128;
    float4 zz = {0.f,0.f,0.f,0.f};
    for (int q = threadIdx.x; q < 128*32; q += 256){
        int n = q >> 5, c4 = (q & 31) * 4;
        *(float4*)(g_C + base + (size_t)n*128 + c4) = *(float4*)&s[n*132 + c4];
        *(float4*)(g_H + base + (size_t)n*128 + c4) = zz;
        *(float4*)(g_m + base + (size_t)n*128 + c4) = zz;
    }
}
__global__ __launch_bounds__(256) void k_outT(float* __restrict__ out){
    extern __shared__ float s[];
    int b = blockIdx.x >> 3, n0 = (blockIdx.x & 7) * 128;
    const float* src = g_H + (size_t)(b*1024 + n0)*128;
    for (int q = threadIdx.x; q < 128*32; q += 256){
        int n = q >> 5, c4 = (q & 31) * 4;
        float4 v = *(const float4*)(src + (size_t)n*128 + c4);
        s[(c4+0)*132 + n] = v.x; s[(c4+1)*132 + n] = v.y;
        s[(c4+2)*132 + n] = v.z; s[(c4+3)*132 + n] = v.w;
    }
    __syncthreads();
    float* dst = out + (size_t)b*128*1024;
    for (int q = threadIdx.x; q < 128*32; q += 256){
        int c = q >> 5, n4 = (q & 31) * 4;
        *(float4*)(dst + (size_t)c*1024 + n0 + n4) = *(float4*)&s[c*132 + n4];
    }
}

// ---------------------------------------------------------------------------
extern "C" void kernel_launch(void* const* d_in, const int* in_sizes, int n_in,
                              void* d_out, int out_size)
{
    const float* x  = (const float*)d_in[0];
    const float* c0 = (const float*)d_in[1];
    const float* W5 = (const float*)d_in[2];
    const float* b5 = (const float*)d_in[3];
    const float* W8 = (const float*)d_in[4];
    const float* b8 = (const float*)d_in[5];
    float* out = (float*)d_out;

    cudaFuncSetAttribute(gemm_mma, cudaFuncAttributeMaxDynamicSharedMemorySize, SMEM_G);
    cudaFuncSetAttribute(k_attn, cudaFuncAttributeMaxDynamicSharedMemorySize, SMEM_ATTN);
    cudaFuncSetAttribute(k_xT,   cudaFuncAttributeMaxDynamicSharedMemorySize, SMEM_TR);
    cudaFuncSetAttribute(k_init, cudaFuncAttributeMaxDynamicSharedMemorySize, SMEM_TR);
    cudaFuncSetAttribute(k_outT, cudaFuncAttributeMaxDynamicSharedMemorySize, SMEM_TR);

    float *pH, *pM, *pZ, *pZH, *pZM, *pY, *pY4, *pG3, *pXT;
    __half *pW5h, *pW5l, *pW8h, *pW8l;
    cudaGetSymbolAddress((void**)&pH,  g_H);
    cudaGetSymbolAddress((void**)&pM,  g_m);
    cudaGetSymbolAddress((void**)&pZ,  g_z);
    cudaGetSymbolAddress((void**)&pZH, g_zh);
    cudaGetSymbolAddress((void**)&pZM, g_zm);
    cudaGetSymbolAddress((void**)&pY,  g_Y);
    cudaGetSymbolAddress((void**)&pY4, g_y4);
    cudaGetSymbolAddress((void**)&pG3, g_g3);
    cudaGetSymbolAddress((void**)&pXT, g_xT);
    cudaGetSymbolAddress((void**)&pW5h, g_W5h);
    cudaGetSymbolAddress((void**)&pW5l, g_W5l);
    cudaGetSymbolAddress((void**)&pW8h, g_W8h);
    cudaGetSymbolAddress((void**)&pW8l, g_W8l);

    // NOTE: grid must cover W5 elements (81920) PLUS W8 elements (262144)
    k_wprep<<<(5*128*128 + 8*128*256 + 255)/256, 256>>>(W5, W8);
    k_xT<<<2048, 256, SMEM_TR>>>(x);
    k_init<<<128, 256, SMEM_TR>>>(c0);

    for (int t = 0; t < TT; t++){
        // conv10..13 on [H|x_t], K=256 -> g_y4
        gemm_mma<<<128, 256, SMEM_G>>>(pH, pXT + (size_t)t*NPIX*128, 2, 4,
            pW8h + (size_t)4*256*128, pW8l + (size_t)4*256*128, b8 + 4*128, 4,
            pY4, 512, 0);
        k_lstm<<<8192, 256>>>();
        // conv1..3 on H, K=128 -> g_Y[0:384)
        gemm_mma<<<128, 256, SMEM_G>>>(pH, pH, 2, 2,
            pW5h, pW5l, b5, 3, pY, 640, 0);
        // conv4..5 on m, K=128 -> g_Y[384:640)
        gemm_mma<<<128, 256, SMEM_G>>>(pM, pM, 2, 2,
            pW5h + (size_t)3*128*128, pW5l + (size_t)3*128*128, b5 + 3*128, 2,
            pY, 640, 384);
        k_attn<<<512, 256, SMEM_ATTN>>>();
        // conv6 on [zh|zm], K=256 -> g_z
        gemm_mma<<<128, 256, SMEM_G>>>(pZH, pZM, 2, 4,
            pW8h, pW8l, b8, 1, pZ, 128, 0);
        // conv7..9 on [H|z], K=256 -> g_g3
        gemm_mma<<<128, 256, SMEM_G>>>(pH, pZ, 2, 4,
            pW8h + (size_t)1*256*128, pW8l + (size_t)1*256*128, b8 + 128, 3,
            pG3, 384, 0);
        k_final<<<8192, 256>>>();
    }
    k_outT<<<128, 256, SMEM_TR>>>(out);
}

// round 7
// speedup vs baseline: 1.9177x; 1.4856x over previous
#include <cuda_runtime.h>
#include <cuda_fp16.h>
#include <math.h>
#include <stdint.h>

#define NPIX 16384
#define TT 16

// ---------------- device scratch -------------------------------------------
__device__ float g_C  [NPIX*128];
__device__ float g_m  [NPIX*128];
__device__ float g_H32[NPIX*128];
__device__ float g_Y  [NPIX*640];               // vh|kh|qh|km|vm (fp32)
__device__ float g_y4 [NPIX*512];               // conv10..13 raw
__device__ float g_g3 [NPIX*384];               // conv7..9 raw
__device__ __half g_Hh[NPIX*128],  g_Hl[NPIX*128];
__device__ __half g_mh[NPIX*128],  g_ml[NPIX*128];
__device__ __half g_zfh[NPIX*128], g_zfl[NPIX*128];   // z (conv6 out)
__device__ __half g_zhh[NPIX*128], g_zhl[NPIX*128];   // zh
__device__ __half g_zmh[NPIX*128], g_zml[NPIX*128];   // zm
__device__ __half g_xTh[(size_t)TT*NPIX*128], g_xTl[(size_t)TT*NPIX*128];
__device__ __half g_W5h[5*128*128], g_W5l[5*128*128];     // [j][k][o]
__device__ __half g_W8h[8*256*128], g_W8l[8*256*128];

__device__ __forceinline__ float sigmoidf_(float x){ return 1.f/(1.f+expf(-x)); }
__device__ __forceinline__ uint32_t smem_u32(const void* p){
    uint32_t a; asm("{ .reg .u64 t; cvta.to.shared.u64 t, %1; cvt.u32.u64 %0, t; }":"=r"(a):"l"(p)); return a;
}
__device__ __forceinline__ void store_hl(__half* Ph, __half* Pl, size_t off, float4 v){
    __half2 h01 = __floats2half2_rn(v.x, v.y);
    __half2 h23 = __floats2half2_rn(v.z, v.w);
    __half2 l01 = __floats2half2_rn(v.x - __low2float(h01), v.y - __high2float(h01));
    __half2 l23 = __floats2half2_rn(v.z - __low2float(h23), v.w - __high2float(h23));
    *(__half2*)(Ph+off) = h01; *(__half2*)(Ph+off+2) = h23;
    *(__half2*)(Pl+off) = l01; *(__half2*)(Pl+off+2) = l23;
}

#define LDSM4(r, a) asm volatile("ldmatrix.sync.aligned.m8n8.x4.shared.b16 {%0,%1,%2,%3}, [%4];" \
  : "=r"((r)[0]),"=r"((r)[1]),"=r"((r)[2]),"=r"((r)[3]) : "r"(a))
#define LDSM4T(r, a) asm volatile("ldmatrix.sync.aligned.m8n8.x4.trans.shared.b16 {%0,%1,%2,%3}, [%4];" \
  : "=r"((r)[0]),"=r"((r)[1]),"=r"((r)[2]),"=r"((r)[3]) : "r"(a))
#define MMA(d, a, b0_, b1_) asm volatile( \
  "mma.sync.aligned.m16n8k16.row.col.f32.f16.f16.f32 {%0,%1,%2,%3},{%4,%5,%6,%7},{%8,%9},{%0,%1,%2,%3};" \
  : "+f"((d)[0]),"+f"((d)[1]),"+f"((d)[2]),"+f"((d)[3]) \
  : "r"((a)[0]),"r"((a)[1]),"r"((a)[2]),"r"((a)[3]), "r"(b0_),"r"(b1_))
#define CPA(dst, src) asm volatile("cp.async.cg.shared.global [%0], [%1], 16;"::"r"(dst),"l"(src))
#define CPCOMMIT()    asm volatile("cp.async.commit_group;")
#define CPWAIT1()     asm volatile("cp.async.wait_group 1;")
#define CPWAIT0()     asm volatile("cp.async.wait_group 0;")

// smem: A: [stage2][half2][128][40] halfs = 4*10240B ; B: [stage2][half2][32][136] = 4*8704B
#define SB_B     40960
#define SMEM_G2  75776

// ---------------- weight prep: fp32 -> k-major fp16 hi/lo ------------------
__global__ void k_wprep(const float* __restrict__ W5, const float* __restrict__ W8){
    int idx = blockIdx.x*blockDim.x + threadIdx.x;
    if (idx < 5*128*128){
        int j = idx/(128*128), r = idx%(128*128), o = r/128, k = r%128;
        float v = W5[idx];
        __half h = __float2half_rn(v);
        __half l = __float2half_rn(v - __half2float(h));
        g_W5h[(j*128 + k)*128 + o] = h;
        g_W5l[(j*128 + k)*128 + o] = l;
        return;
    }
    int i2 = idx - 5*128*128;
    if (i2 >= 0 && i2 < 8*128*256){
        int j = i2/(128*256), r = i2%(128*256), o = r/256, k = r%256;
        float v = W8[i2];
        __half h = __float2half_rn(v);
        __half l = __float2half_rn(v - __half2float(h));
        g_W8h[((size_t)j*256 + k)*128 + o] = h;
        g_W8l[((size_t)j*256 + k)*128 + o] = l;
    }
}

// ---------------------------------------------------------------------------
// GEMM v2: one (pixel-tile, conv j) per CTA, cp.async pipelined, fp16 hi/lo x3.
// A source: j >= jA1start -> (A2h,A2l); else k<S -> (A0h,A0l) else (A1h,A1l).
// ---------------------------------------------------------------------------
__global__ __launch_bounds__(256, 2)
void gemm2(const __half* __restrict__ A0h, const __half* __restrict__ A0l,
           const __half* __restrict__ A1h, const __half* __restrict__ A1l, int S,
           const __half* __restrict__ A2h, const __half* __restrict__ A2l, int jA1start,
           int K, const __half* __restrict__ Wh, const __half* __restrict__ Wl,
           const float* __restrict__ bias,
           float* __restrict__ outF, int outStride, int outColOff,
           __half* __restrict__ outHh, __half* __restrict__ outHl)
{
    extern __shared__ char smem[];
    const uint32_t sbase = smem_u32(smem);
    const int tid = threadIdx.x, wid = tid >> 5, lane = tid & 31;
    const int p0 = blockIdx.x * 128;
    const int j  = blockIdx.y;

    const int wm = wid >> 2, wn = wid & 3;         // warp tile 64(M) x 32(N)
    const int m0 = wm*64, n0 = wn*32;
    const int l15 = lane & 15, lH = (lane >> 4) << 3;

    const __half* wbH = Wh + (size_t)j*K*128;
    const __half* wbL = Wl + (size_t)j*K*128;

    auto load_chunk = [&](int ch, int s){
        const int k0 = ch*32;
        const __half *srcH, *srcL; int koff;
        if (j >= jA1start){ srcH = A2h; srcL = A2l; koff = k0; }
        else if (k0 < S)  { srcH = A0h; srcL = A0l; koff = k0; }
        else              { srcH = A1h; srcL = A1l; koff = k0 - S; }
        #pragma unroll
        for (int q = tid; q < 1024; q += 256){
            int h = q >> 9, e = q & 511, r = e >> 2, seg = e & 3;
            uint32_t dst = sbase + (uint32_t)((s*2 + h)*10240 + r*80 + seg*16);
            const __half* src = (h ? srcL : srcH) + (size_t)(p0 + r)*128 + koff + seg*8;
            CPA(dst, src);
        }
        #pragma unroll
        for (int q = tid; q < 1024; q += 256){
            int h = q >> 9, e = q & 511, r = e >> 4, seg = e & 15;
            uint32_t dst = sbase + SB_B + (uint32_t)((s*2 + h)*8704 + r*272 + seg*16);
            const __half* src = (h ? wbL : wbH) + (size_t)(k0 + r)*128 + seg*8;
            CPA(dst, src);
        }
    };

    float d[4][4][4];
    #pragma unroll
    for (int a=0;a<4;a++){
        #pragma unroll
        for (int b=0;b<4;b++){
            #pragma unroll
            for (int e=0;e<4;e++) d[a][b][e]=0.f; } }

    const int CH = K >> 5;
    load_chunk(0, 0); CPCOMMIT();
    if (CH > 1) load_chunk(1, 1);
    CPCOMMIT();

    for (int ch = 0; ch < CH; ch++){
        const int s = ch & 1;
        CPWAIT1();
        __syncthreads();
        #pragma unroll
        for (int ks = 0; ks < 2; ks++){
            const int k = ks*16;
            uint32_t AH[4][4], AL[4][4], BH[2][4], BL[2][4];
            #pragma unroll
            for (int mi = 0; mi < 4; mi++){
                uint32_t ad = sbase + (uint32_t)(s*20480 + ((m0 + mi*16 + l15)*40 + k + lH)*2);
                LDSM4(AH[mi], ad);
                LDSM4(AL[mi], ad + 10240);
            }
            #pragma unroll
            for (int bt = 0; bt < 2; bt++){
                uint32_t bd = sbase + SB_B + (uint32_t)(s*17408 + ((k + l15)*136 + n0 + bt*16 + lH)*2);
                LDSM4T(BH[bt], bd);
                LDSM4T(BL[bt], bd + 8704);
            }
            #pragma unroll
            for (int mi = 0; mi < 4; mi++){
                #pragma unroll
                for (int nj = 0; nj < 4; nj++){
                    const int t = nj >> 1, o = (nj & 1)*2;
                    MMA(d[mi][nj], AH[mi], BH[t][o], BH[t][o+1]);
                    MMA(d[mi][nj], AL[mi], BH[t][o], BH[t][o+1]);
                    MMA(d[mi][nj], AH[mi], BL[t][o], BL[t][o+1]);
                }
            }
        }
        __syncthreads();
        if (ch + 2 < CH) load_chunk(ch + 2, s);
        CPCOMMIT();
    }
    CPWAIT0();
    __syncthreads();

    // ---- epilogue: frags -> smem -> coalesced stores ----------------------
    float* sbuf = (float*)smem;                   // [64][132]
    #pragma unroll
    for (int h2 = 0; h2 < 2; h2++){
        __syncthreads();
        if (wm == h2){
            #pragma unroll
            for (int mi = 0; mi < 4; mi++){
                int r0 = mi*16 + (lane>>2);
                #pragma unroll
                for (int nj = 0; nj < 4; nj++){
                    int c = n0 + nj*8 + ((lane&3)<<1);
                    sbuf[r0*132 + c]       = d[mi][nj][0];
                    sbuf[r0*132 + c + 1]   = d[mi][nj][1];
                    sbuf[(r0+8)*132 + c]   = d[mi][nj][2];
                    sbuf[(r0+8)*132 + c+1] = d[mi][nj][3];
                }
            }
        }
        __syncthreads();
        for (int q = tid; q < 64*32; q += 256){
            int r = q >> 5, c4 = (q & 31) << 2;
            float4 v = *(float4*)&sbuf[r*132 + c4];
            float4 bv = *(const float4*)&bias[j*128 + c4];
            v.x += bv.x; v.y += bv.y; v.z += bv.z; v.w += bv.w;
            int prow = p0 + h2*64 + r;
            if (outF)
                *(float4*)(outF + (size_t)prow*outStride + outColOff + j*128 + c4) = v;
            if (outHh)
                store_hl(outHh, outHl, (size_t)prow*128 + j*128 + c4, v);
        }
    }
}

// ---------------- LSTM gates (after conv10..13), fused fp16 out ------------
__global__ void k_lstm(){
    int idx = blockIdx.x*blockDim.x + threadIdx.x;   // NPIX*32
    int p = idx >> 5, c4 = (idx & 31) << 2;
    const float* y = g_y4 + (size_t)p*512 + c4;
    float4 A  = *(const float4*)(y);
    float4 GA = *(const float4*)(y + 128);
    float4 GV = *(const float4*)(y + 256);
    float4 A1 = *(const float4*)(y + 384);
    size_t o = (size_t)p*128 + c4;
    float4 C = *(float4*)(g_C + o);
    float4 cs, h;
    cs.x = C.x*sigmoidf_(A.x) + sigmoidf_(GA.x)*tanhf(GV.x); h.x = sigmoidf_(A1.x)*tanhf(cs.x);
    cs.y = C.y*sigmoidf_(A.y) + sigmoidf_(GA.y)*tanhf(GV.y); h.y = sigmoidf_(A1.y)*tanhf(cs.y);
    cs.z = C.z*sigmoidf_(A.z) + sigmoidf_(GA.z)*tanhf(GV.z); h.z = sigmoidf_(A1.z)*tanhf(cs.z);
    cs.w = C.w*sigmoidf_(A.w) + sigmoidf_(GA.w)*tanhf(GV.w); h.w = sigmoidf_(A1.w)*tanhf(cs.w);
    *(float4*)(g_C + o) = cs;
    store_hl(g_Hh, g_Hl, o, h);
}

// ---------------- final gates (after conv7..9) -----------------------------
__global__ void k_final(){
    int idx = blockIdx.x*blockDim.x + threadIdx.x;
    int p = idx >> 5, c4 = (idx & 31) << 2;
    const float* y = g_g3 + (size_t)p*384 + c4;
    float4 OT = *(const float4*)(y);
    float4 GT = *(const float4*)(y + 128);
    float4 IT = *(const float4*)(y + 256);
    size_t o = (size_t)p*128 + c4;
    float4 M = *(float4*)(g_m + o);
    float4 mt, h;
    { float it = sigmoidf_(IT.x); mt.x = tanhf(GT.x)*it + (1.f-it)*M.x; h.x = sigmoidf_(OT.x)*mt.x; }
    { float it = sigmoidf_(IT.y); mt.y = tanhf(GT.y)*it + (1.f-it)*M.y; h.y = sigmoidf_(OT.y)*mt.y; }
    { float it = sigmoidf_(IT.z); mt.z = tanhf(GT.z)*it + (1.f-it)*M.z; h.z = sigmoidf_(OT.z)*mt.z; }
    { float it = sigmoidf_(IT.w); mt.w = tanhf(GT.w)*it + (1.f-it)*M.w; h.w = sigmoidf_(OT.w)*mt.w; }
    *(float4*)(g_m + o) = mt;
    *(float4*)(g_H32 + o) = h;
    store_hl(g_mh, g_ml, o, mt);
    store_hl(g_Hh, g_Hl, o, h);
}

// ---------------- attention -------------------------------------------------
#define AT_P 132
#define SMEM_ATTN (5*32*AT_P*4)
__global__ __launch_bounds__(256) void k_attn(){
    extern __shared__ float s[];
    float* s_vh = s;
    float* s_kh = s + 1*32*AT_P;
    float* s_qt = s + 2*32*AT_P;
    float* s_km = s + 3*32*AT_P;
    float* s_vm = s + 4*32*AT_P;
    const int tid = threadIdx.x;
    const int b = blockIdx.x >> 5, h = blockIdx.x & 31;
    const int r0 = b*1024 + h*32;

    for (int q = tid; q < 32*32; q += 256){
        int w = q >> 5, c4 = (q & 31) * 4;
        const float* row = g_Y + (size_t)(r0 + w)*640;
        float4 v;
        v = *(const float4*)(row +   0 + c4); *(float4*)&s_vh[w*AT_P+c4] = v;
        v = *(const float4*)(row + 128 + c4); *(float4*)&s_kh[w*AT_P+c4] = v;
        v = *(const float4*)(row + 384 + c4); *(float4*)&s_km[w*AT_P+c4] = v;
        v = *(const float4*)(row + 512 + c4); *(float4*)&s_vm[w*AT_P+c4] = v;
        const float* qrow = g_Y + (size_t)(b*1024 + w*32 + h)*640 + 256;   // transposed q
        v = *(const float4*)(qrow + c4);      *(float4*)&s_qt[w*AT_P+c4] = v;
    }
    __syncthreads();

    const int wid = tid >> 5, lane = tid & 31;           // lane = w
    for (int i = 0; i < 16; i++){
        int c = wid + 8*i;
        float qv = s_qt[lane*AT_P + c];
        float s1 = s_kh[lane*AT_P + c] * qv;
        float mx = s1;
        #pragma unroll
        for (int o = 16; o; o >>= 1) mx = fmaxf(mx, __shfl_xor_sync(0xffffffffu, mx, o));
        float e1 = expf(s1 - mx), sm = e1;
        #pragma unroll
        for (int o = 16; o; o >>= 1) sm += __shfl_xor_sync(0xffffffffu, sm, o);
        s_vh[lane*AT_P + c] *= (e1 / sm);                // zh
        float s2 = qv * s_km[lane*AT_P + c];
        float mx2 = s2;
        #pragma unroll
        for (int o = 16; o; o >>= 1) mx2 = fmaxf(mx2, __shfl_xor_sync(0xffffffffu, mx2, o));
        float e2 = expf(s2 - mx2), sm2 = e2;
        #pragma unroll
        for (int o = 16; o; o >>= 1) sm2 += __shfl_xor_sync(0xffffffffu, sm2, o);
        s_vm[lane*AT_P + c] *= (e2 / sm2);               // zm
    }
    __syncthreads();
    for (int q = tid; q < 32*32; q += 256){
        int w = q >> 5, c4 = (q & 31) * 4;
        size_t o = (size_t)(r0 + w)*128 + c4;
        store_hl(g_zhh, g_zhl, o, *(float4*)&s_vh[w*AT_P + c4]);
        store_hl(g_zmh, g_zml, o, *(float4*)&s_vm[w*AT_P + c4]);
    }
}

// ---------------- layout transposes ----------------------------------------
#define SMEM_TR (128*132*4)
__global__ __launch_bounds__(256) void k_xT(const float* __restrict__ x){
    extern __shared__ float s[];
    int bid = blockIdx.x;
    int b = bid >> 7, t = (bid >> 3) & 15, n0 = (bid & 7) * 128;
    const float* src = x + (size_t)(b*16 + t)*128*1024;
    for (int q = threadIdx.x; q < 128*32; q += 256){
        int c = q >> 5, n4 = (q & 31) * 4;
        float4 v = *(const float4*)(src + (size_t)c*1024 + n0 + n4);
        s[(n4+0)*132 + c] = v.x; s[(n4+1)*132 + c] = v.y;
        s[(n4+2)*132 + c] = v.z; s[(n4+3)*132 + c] = v.w;
    }
    __syncthreads();
    size_t base = ((size_t)t*NPIX + b*1024 + n0)*128;
    for (int q = threadIdx.x; q < 128*32; q += 256){
        int n = q >> 5, c4 = (q & 31) * 4;
        store_hl(g_xTh, g_xTl, base + (size_t)n*128 + c4, *(float4*)&s[n*132 + c4]);
    }
}
__global__ __launch_bounds__(256) void k_init(const float* __restrict__ c0){
    extern __shared__ float s[];
    int b = blockIdx.x >> 3, n0 = (blockIdx.x & 7) * 128;
    const float* src = c0 + (size_t)b*128*1024;
    for (int q = threadIdx.x; q < 128*32; q += 256){
        int c = q >> 5, n4 = (q & 31) * 4;
        float4 v = *(const float4*)(src + (size_t)c*1024 + n0 + n4);
        s[(n4+0)*132 + c] = v.x; s[(n4+1)*132 + c] = v.y;
        s[(n4+2)*132 + c] = v.z; s[(n4+3)*132 + c] = v.w;
    }
    __syncthreads();
    size_t base = (size_t)(b*1024 + n0)*128;
    float4 zz = {0.f,0.f,0.f,0.f};
    for (int q = threadIdx.x; q < 128*32; q += 256){
        int n = q >> 5, c4 = (q & 31) * 4;
        size_t o = base + (size_t)n*128 + c4;
        *(float4*)(g_C + o) = *(float4*)&s[n*132 + c4];
        *(float4*)(g_m + o) = zz;
        store_hl(g_Hh, g_Hl, o, zz);
        store_hl(g_mh, g_ml, o, zz);
    }
}
__global__ __launch_bounds__(256) void k_outT(float* __restrict__ out){
    extern __shared__ float s[];
    int b = blockIdx.x >> 3, n0 = (blockIdx.x & 7) * 128;
    const float* src = g_H32 + (size_t)(b*1024 + n0)*128;
    for (int q = threadIdx.x; q < 128*32; q += 256){
        int n = q >> 5, c4 = (q & 31) * 4;
        float4 v = *(const float4*)(src + (size_t)n*128 + c4);
        s[(c4+0)*132 + n] = v.x; s[(c4+1)*132 + n] = v.y;
        s[(c4+2)*132 + n] = v.z; s[(c4+3)*132 + n] = v.w;
    }
    __syncthreads();
    float* dst = out + (size_t)b*128*1024;
    for (int q = threadIdx.x; q < 128*32; q += 256){
        int c = q >> 5, n4 = (q & 31) * 4;
        *(float4*)(dst + (size_t)c*1024 + n0 + n4) = *(float4*)&s[c*132 + n4];
    }
}

// ---------------------------------------------------------------------------
extern "C" void kernel_launch(void* const* d_in, const int* in_sizes, int n_in,
                              void* d_out, int out_size)
{
    const float* x  = (const float*)d_in[0];
    const float* c0 = (const float*)d_in[1];
    const float* W5 = (const float*)d_in[2];
    const float* b5 = (const float*)d_in[3];
    const float* W8 = (const float*)d_in[4];
    const float* b8 = (const float*)d_in[5];
    float* out = (float*)d_out;

    cudaFuncSetAttribute(gemm2, cudaFuncAttributeMaxDynamicSharedMemorySize, SMEM_G2);
    cudaFuncSetAttribute(k_attn, cudaFuncAttributeMaxDynamicSharedMemorySize, SMEM_ATTN);
    cudaFuncSetAttribute(k_xT,   cudaFuncAttributeMaxDynamicSharedMemorySize, SMEM_TR);
    cudaFuncSetAttribute(k_init, cudaFuncAttributeMaxDynamicSharedMemorySize, SMEM_TR);
    cudaFuncSetAttribute(k_outT, cudaFuncAttributeMaxDynamicSharedMemorySize, SMEM_TR);

    float *pY, *pY4, *pG3;
    __half *pHh,*pHl,*pmh,*pml,*pzfh,*pzfl,*pzhh,*pzhl,*pzmh,*pzml,*pxTh,*pxTl;
    __half *pW5h,*pW5l,*pW8h,*pW8l;
    cudaGetSymbolAddress((void**)&pY,  g_Y);
    cudaGetSymbolAddress((void**)&pY4, g_y4);
    cudaGetSymbolAddress((void**)&pG3, g_g3);
    cudaGetSymbolAddress((void**)&pHh, g_Hh);  cudaGetSymbolAddress((void**)&pHl, g_Hl);
    cudaGetSymbolAddress((void**)&pmh, g_mh);  cudaGetSymbolAddress((void**)&pml, g_ml);
    cudaGetSymbolAddress((void**)&pzfh,g_zfh); cudaGetSymbolAddress((void**)&pzfl,g_zfl);
    cudaGetSymbolAddress((void**)&pzhh,g_zhh); cudaGetSymbolAddress((void**)&pzhl,g_zhl);
    cudaGetSymbolAddress((void**)&pzmh,g_zmh); cudaGetSymbolAddress((void**)&pzml,g_zml);
    cudaGetSymbolAddress((void**)&pxTh,g_xTh); cudaGetSymbolAddress((void**)&pxTl,g_xTl);
    cudaGetSymbolAddress((void**)&pW5h,g_W5h); cudaGetSymbolAddress((void**)&pW5l,g_W5l);
    cudaGetSymbolAddress((void**)&pW8h,g_W8h); cudaGetSymbolAddress((void**)&pW8l,g_W8l);

    k_wprep<<<(5*128*128 + 8*128*256 + 255)/256, 256>>>(W5, W8);
    k_xT<<<2048, 256, SMEM_TR>>>(x);
    k_init<<<128, 256, SMEM_TR>>>(c0);

    for (int t = 0; t < TT; t++){
        const size_t xo = (size_t)t*NPIX*128;
        // conv10..13 on [H | x_t], K=256 -> y4
        gemm2<<<dim3(128,4), 256, SMEM_G2>>>(pHh, pHl, pxTh + xo, pxTl + xo, 128,
            nullptr, nullptr, 4, 256,
            pW8h + (size_t)4*256*128, pW8l + (size_t)4*256*128, b8 + 4*128,
            pY4, 512, 0, nullptr, nullptr);
        k_lstm<<<2048, 256>>>();
        // conv1..3 on H, conv4..5 on m, K=128 -> Y
        gemm2<<<dim3(128,5), 256, SMEM_G2>>>(pHh, pHl, nullptr, nullptr, 128,
            pmh, pml, 3, 128,
            pW5h, pW5l, b5,
            pY, 640, 0, nullptr, nullptr);
        k_attn<<<512, 256, SMEM_ATTN>>>();
        // conv6 on [zh | zm], K=256 -> z (fp16 pair)
        gemm2<<<dim3(128,1), 256, SMEM_G2>>>(pzhh, pzhl, pzmh, pzml, 128,
            nullptr, nullptr, 9, 256,
            pW8h, pW8l, b8,
            nullptr, 0, 0, pzfh, pzfl);
        // conv7..9 on [H | z], K=256 -> g3
        gemm2<<<dim3(128,3), 256, SMEM_G2>>>(pHh, pHl, pzfh, pzfl, 128,
            nullptr, nullptr, 9, 256,
            pW8h + (size_t)1*256*128, pW8l + (size_t)1*256*128, b8 + 128,
            pG3, 384, 0, nullptr, nullptr);
        k_final<<<2048, 256>>>();
    }
    k_outT<<<128, 256, SMEM_TR>>>(out);
}

// round 8
// speedup vs baseline: 1.9749x; 1.0298x over previous
#include <cuda_runtime.h>
#include <cuda_fp16.h>
#include <math.h>
#include <stdint.h>

#define NPIX 16384
#define TT 16

// ---------------- device scratch -------------------------------------------
__device__ float g_C  [NPIX*128];
__device__ float g_m  [NPIX*128];
__device__ float g_H32[NPIX*128];
__device__ float g_Y  [NPIX*640];               // vh|kh|qh|km|vm (fp32)
__device__ float g_y4 [NPIX*512];               // conv10..13 raw
__device__ float g_g3 [NPIX*384];               // conv7..9 raw
__device__ __half g_Hh[NPIX*128],  g_Hl[NPIX*128];
__device__ __half g_mh[NPIX*128],  g_ml[NPIX*128];
__device__ __half g_zfh[NPIX*128], g_zfl[NPIX*128];   // z (conv6 out)
__device__ __half g_zhh[NPIX*128], g_zhl[NPIX*128];   // zh
__device__ __half g_zmh[NPIX*128], g_zml[NPIX*128];   // zm
__device__ __half g_xTh[(size_t)TT*NPIX*128], g_xTl[(size_t)TT*NPIX*128];
__device__ __half g_W5h[5*128*128], g_W5l[5*128*128];     // [j][k][o]
__device__ __half g_W8h[8*256*128], g_W8l[8*256*128];

__device__ __forceinline__ float sigmoidf_(float x){ return 1.f/(1.f+expf(-x)); }
__device__ __forceinline__ uint32_t smem_u32(const void* p){
    uint32_t a; asm("{ .reg .u64 t; cvta.to.shared.u64 t, %1; cvt.u32.u64 %0, t; }":"=r"(a):"l"(p)); return a;
}
__device__ __forceinline__ void store_hl(__half* Ph, __half* Pl, size_t off, float4 v){
    __half2 h01 = __floats2half2_rn(v.x, v.y);
    __half2 h23 = __floats2half2_rn(v.z, v.w);
    __half2 l01 = __floats2half2_rn(v.x - __low2float(h01), v.y - __high2float(h01));
    __half2 l23 = __floats2half2_rn(v.z - __low2float(h23), v.w - __high2float(h23));
    *(__half2*)(Ph+off) = h01; *(__half2*)(Ph+off+2) = h23;
    *(__half2*)(Pl+off) = l01; *(__half2*)(Pl+off+2) = l23;
}

#define LDSM4(r, a) asm volatile("ldmatrix.sync.aligned.m8n8.x4.shared.b16 {%0,%1,%2,%3}, [%4];" \
  : "=r"((r)[0]),"=r"((r)[1]),"=r"((r)[2]),"=r"((r)[3]) : "r"(a))
#define LDSM4T(r, a) asm volatile("ldmatrix.sync.aligned.m8n8.x4.trans.shared.b16 {%0,%1,%2,%3}, [%4];" \
  : "=r"((r)[0]),"=r"((r)[1]),"=r"((r)[2]),"=r"((r)[3]) : "r"(a))
#define MMA(d, a, b0_, b1_) asm volatile( \
  "mma.sync.aligned.m16n8k16.row.col.f32.f16.f16.f32 {%0,%1,%2,%3},{%4,%5,%6,%7},{%8,%9},{%0,%1,%2,%3};" \
  : "+f"((d)[0]),"+f"((d)[1]),"+f"((d)[2]),"+f"((d)[3]) \
  : "r"((a)[0]),"r"((a)[1]),"r"((a)[2]),"r"((a)[3]), "r"(b0_),"r"(b1_))
#define CPA(dst, src) asm volatile("cp.async.cg.shared.global [%0], [%1], 16;"::"r"(dst),"l"(src))
#define CPCOMMIT()    asm volatile("cp.async.commit_group;")
#define CPWAIT1()     asm volatile("cp.async.wait_group 1;")
#define CPWAIT0()     asm volatile("cp.async.wait_group 0;")

// smem: A: [stage2][hi/lo][64][40] halfs = 4*5120B = 20480
//       B: [stage2][hi/lo][32][136] halfs = 4*8704B = 34816
#define SB_B     20480
#define SMEM_G2  55296

// ---------------- weight prep: fp32 -> k-major fp16 hi/lo ------------------
__global__ void k_wprep(const float* __restrict__ W5, const float* __restrict__ W8){
    int idx = blockIdx.x*blockDim.x + threadIdx.x;
    if (idx < 5*128*128){
        int j = idx/(128*128), r = idx%(128*128), o = r/128, k = r%128;
        float v = W5[idx];
        __half h = __float2half_rn(v);
        __half l = __float2half_rn(v - __half2float(h));
        g_W5h[(j*128 + k)*128 + o] = h;
        g_W5l[(j*128 + k)*128 + o] = l;
        return;
    }
    int i2 = idx - 5*128*128;
    if (i2 >= 0 && i2 < 8*128*256){
        int j = i2/(128*256), r = i2%(128*256), o = r/256, k = r%256;
        float v = W8[i2];
        __half h = __float2half_rn(v);
        __half l = __float2half_rn(v - __half2float(h));
        g_W8h[((size_t)j*256 + k)*128 + o] = h;
        g_W8l[((size_t)j*256 + k)*128 + o] = l;
    }
}

// ---------------------------------------------------------------------------
// GEMM v3: 64-pixel x 128-out CTA tile, warp tile 32x32, cp.async 2-stage,
// fp16 hi/lo x3 MMAs. grid = (256 pixel tiles, NJ convs).
// A source: j >= jA1start -> (A2h,A2l); else k<S -> (A0h,A0l) else (A1h,A1l).
// ---------------------------------------------------------------------------
__global__ __launch_bounds__(256, 3)
void gemm2(const __half* __restrict__ A0h, const __half* __restrict__ A0l,
           const __half* __restrict__ A1h, const __half* __restrict__ A1l, int S,
           const __half* __restrict__ A2h, const __half* __restrict__ A2l, int jA1start,
           int K, const __half* __restrict__ Wh, const __half* __restrict__ Wl,
           const float* __restrict__ bias,
           float* __restrict__ outF, int outStride, int outColOff,
           __half* __restrict__ outHh, __half* __restrict__ outHl)
{
    extern __shared__ char smem[];
    const uint32_t sbase = smem_u32(smem);
    const int tid = threadIdx.x, wid = tid >> 5, lane = tid & 31;
    const int p0 = blockIdx.x * 64;
    const int j  = blockIdx.y;

    const int wm = wid >> 2, wn = wid & 3;         // warp tile 32(M) x 32(N)
    const int m0 = wm*32, n0 = wn*32;
    const int l15 = lane & 15, lH = (lane >> 4) << 3;

    const __half* wbH = Wh + (size_t)j*K*128;
    const __half* wbL = Wl + (size_t)j*K*128;

    auto load_chunk = [&](int ch, int s){
        const int k0 = ch*32;
        const __half *srcH, *srcL; int koff;
        if (j >= jA1start){ srcH = A2h; srcL = A2l; koff = k0; }
        else if (k0 < S)  { srcH = A0h; srcL = A0l; koff = k0; }
        else              { srcH = A1h; srcL = A1l; koff = k0 - S; }
        // A: 2 matrices x 64 rows x 4 x 16B
        #pragma unroll
        for (int q = tid; q < 512; q += 256){
            int h = q >> 8, e = q & 255, r = e >> 2, seg = e & 3;
            uint32_t dst = sbase + (uint32_t)((s*2 + h)*5120 + r*80 + seg*16);
            const __half* src = (h ? srcL : srcH) + (size_t)(p0 + r)*128 + koff + seg*8;
            CPA(dst, src);
        }
        // B: 2 matrices x 32 rows x 16 x 16B
        #pragma unroll
        for (int q = tid; q < 1024; q += 256){
            int h = q >> 9, e = q & 511, r = e >> 4, seg = e & 15;
            uint32_t dst = sbase + SB_B + (uint32_t)((s*2 + h)*8704 + r*272 + seg*16);
            const __half* src = (h ? wbL : wbH) + (size_t)(k0 + r)*128 + seg*8;
            CPA(dst, src);
        }
    };

    float d[2][4][4];
    #pragma unroll
    for (int a=0;a<2;a++){
        #pragma unroll
        for (int b=0;b<4;b++){
            #pragma unroll
            for (int e=0;e<4;e++) d[a][b][e]=0.f; } }

    const int CH = K >> 5;
    load_chunk(0, 0); CPCOMMIT();
    if (CH > 1) load_chunk(1, 1);
    CPCOMMIT();

    for (int ch = 0; ch < CH; ch++){
        const int s = ch & 1;
        CPWAIT1();
        __syncthreads();
        #pragma unroll
        for (int ks = 0; ks < 2; ks++){
            const int k = ks*16;
            uint32_t AH[2][4], AL[2][4], BH[2][4], BL[2][4];
            #pragma unroll
            for (int mi = 0; mi < 2; mi++){
                uint32_t ad = sbase + (uint32_t)(s*10240 + ((m0 + mi*16 + l15)*40 + k + lH)*2);
                LDSM4(AH[mi], ad);
                LDSM4(AL[mi], ad + 5120);
            }
            #pragma unroll
            for (int bt = 0; bt < 2; bt++){
                uint32_t bd = sbase + SB_B + (uint32_t)(s*17408 + ((k + l15)*136 + n0 + bt*16 + lH)*2);
                LDSM4T(BH[bt], bd);
                LDSM4T(BL[bt], bd + 8704);
            }
            #pragma unroll
            for (int mi = 0; mi < 2; mi++){
                #pragma unroll
                for (int nj = 0; nj < 4; nj++){
                    const int t = nj >> 1, o = (nj & 1)*2;
                    MMA(d[mi][nj], AH[mi], BH[t][o], BH[t][o+1]);
                    MMA(d[mi][nj], AL[mi], BH[t][o], BH[t][o+1]);
                    MMA(d[mi][nj], AH[mi], BL[t][o], BL[t][o+1]);
                }
            }
        }
        __syncthreads();
        if (ch + 2 < CH) load_chunk(ch + 2, s);
        CPCOMMIT();
    }
    CPWAIT0();
    __syncthreads();

    // ---- epilogue: frags -> smem [32][132] -> coalesced stores ------------
    float* sbuf = (float*)smem;
    #pragma unroll
    for (int h2 = 0; h2 < 2; h2++){
        __syncthreads();
        if (wm == h2){
            #pragma unroll
            for (int mi = 0; mi < 2; mi++){
                int r0 = mi*16 + (lane>>2);
                #pragma unroll
                for (int nj = 0; nj < 4; nj++){
                    int c = n0 + nj*8 + ((lane&3)<<1);
                    sbuf[r0*132 + c]       = d[mi][nj][0];
                    sbuf[r0*132 + c + 1]   = d[mi][nj][1];
                    sbuf[(r0+8)*132 + c]   = d[mi][nj][2];
                    sbuf[(r0+8)*132 + c+1] = d[mi][nj][3];
                }
            }
        }
        __syncthreads();
        for (int q = tid; q < 32*32; q += 256){
            int r = q >> 5, c4 = (q & 31) << 2;
            float4 v = *(float4*)&sbuf[r*132 + c4];
            float4 bv = *(const float4*)&bias[j*128 + c4];
            v.x += bv.x; v.y += bv.y; v.z += bv.z; v.w += bv.w;
            int prow = p0 + h2*32 + r;
            if (outF)
                *(float4*)(outF + (size_t)prow*outStride + outColOff + j*128 + c4) = v;
            if (outHh)
                store_hl(outHh, outHl, (size_t)prow*128 + j*128 + c4, v);
        }
    }
}

// ---------------- LSTM gates (after conv10..13), fused fp16 out ------------
__global__ void k_lstm(){
    int idx = blockIdx.x*blockDim.x + threadIdx.x;   // NPIX*32
    int p = idx >> 5, c4 = (idx & 31) << 2;
    const float* y = g_y4 + (size_t)p*512 + c4;
    float4 A  = *(const float4*)(y);
    float4 GA = *(const float4*)(y + 128);
    float4 GV = *(const float4*)(y + 256);
    float4 A1 = *(const float4*)(y + 384);
    size_t o = (size_t)p*128 + c4;
    float4 C = *(float4*)(g_C + o);
    float4 cs, h;
    cs.x = C.x*sigmoidf_(A.x) + sigmoidf_(GA.x)*tanhf(GV.x); h.x = sigmoidf_(A1.x)*tanhf(cs.x);
    cs.y = C.y*sigmoidf_(A.y) + sigmoidf_(GA.y)*tanhf(GV.y); h.y = sigmoidf_(A1.y)*tanhf(cs.y);
    cs.z = C.z*sigmoidf_(A.z) + sigmoidf_(GA.z)*tanhf(GV.z); h.z = sigmoidf_(A1.z)*tanhf(cs.z);
    cs.w = C.w*sigmoidf_(A.w) + sigmoidf_(GA.w)*tanhf(GV.w); h.w = sigmoidf_(A1.w)*tanhf(cs.w);
    *(float4*)(g_C + o) = cs;
    store_hl(g_Hh, g_Hl, o, h);
}

// ---------------- final gates (after conv7..9) -----------------------------
__global__ void k_final(){
    int idx = blockIdx.x*blockDim.x + threadIdx.x;
    int p = idx >> 5, c4 = (idx & 31) << 2;
    const float* y = g_g3 + (size_t)p*384 + c4;
    float4 OT = *(const float4*)(y);
    float4 GT = *(const float4*)(y + 128);
    float4 IT = *(const float4*)(y + 256);
    size_t o = (size_t)p*128 + c4;
    float4 M = *(float4*)(g_m + o);
    float4 mt, h;
    { float it = sigmoidf_(IT.x); mt.x = tanhf(GT.x)*it + (1.f-it)*M.x; h.x = sigmoidf_(OT.x)*mt.x; }
    { float it = sigmoidf_(IT.y); mt.y = tanhf(GT.y)*it + (1.f-it)*M.y; h.y = sigmoidf_(OT.y)*mt.y; }
    { float it = sigmoidf_(IT.z); mt.z = tanhf(GT.z)*it + (1.f-it)*M.z; h.z = sigmoidf_(OT.z)*mt.z; }
    { float it = sigmoidf_(IT.w); mt.w = tanhf(GT.w)*it + (1.f-it)*M.w; h.w = sigmoidf_(OT.w)*mt.w; }
    *(float4*)(g_m + o) = mt;
    *(float4*)(g_H32 + o) = h;
    store_hl(g_mh, g_ml, o, mt);
    store_hl(g_Hh, g_Hl, o, h);
}

// ---------------- attention -------------------------------------------------
#define AT_P 132
#define SMEM_ATTN (5*32*AT_P*4)
__global__ __launch_bounds__(256) void k_attn(){
    extern __shared__ float s[];
    float* s_vh = s;
    float* s_kh = s + 1*32*AT_P;
    float* s_qt = s + 2*32*AT_P;
    float* s_km = s + 3*32*AT_P;
    float* s_vm = s + 4*32*AT_P;
    const int tid = threadIdx.x;
    const int b = blockIdx.x >> 5, h = blockIdx.x & 31;
    const int r0 = b*1024 + h*32;

    for (int q = tid; q < 32*32; q += 256){
        int w = q >> 5, c4 = (q & 31) * 4;
        const float* row = g_Y + (size_t)(r0 + w)*640;
        float4 v;
        v = *(const float4*)(row +   0 + c4); *(float4*)&s_vh[w*AT_P+c4] = v;
        v = *(const float4*)(row + 128 + c4); *(float4*)&s_kh[w*AT_P+c4] = v;
        v = *(const float4*)(row + 384 + c4); *(float4*)&s_km[w*AT_P+c4] = v;
        v = *(const float4*)(row + 512 + c4); *(float4*)&s_vm[w*AT_P+c4] = v;
        const float* qrow = g_Y + (size_t)(b*1024 + w*32 + h)*640 + 256;   // transposed q
        v = *(const float4*)(qrow + c4);      *(float4*)&s_qt[w*AT_P+c4] = v;
    }
    __syncthreads();

    const int wid = tid >> 5, lane = tid & 31;           // lane = w
    for (int i = 0; i < 16; i++){
        int c = wid + 8*i;
        float qv = s_qt[lane*AT_P + c];
        float s1 = s_kh[lane*AT_P + c] * qv;
        float mx = s1;
        #pragma unroll
        for (int o = 16; o; o >>= 1) mx = fmaxf(mx, __shfl_xor_sync(0xffffffffu, mx, o));
        float e1 = expf(s1 - mx), sm = e1;
        #pragma unroll
        for (int o = 16; o; o >>= 1) sm += __shfl_xor_sync(0xffffffffu, sm, o);
        s_vh[lane*AT_P + c] *= (e1 / sm);                // zh
        float s2 = qv * s_km[lane*AT_P + c];
        float mx2 = s2;
        #pragma unroll
        for (int o = 16; o; o >>= 1) mx2 = fmaxf(mx2, __shfl_xor_sync(0xffffffffu, mx2, o));
        float e2 = expf(s2 - mx2), sm2 = e2;
        #pragma unroll
        for (int o = 16; o; o >>= 1) sm2 += __shfl_xor_sync(0xffffffffu, sm2, o);
        s_vm[lane*AT_P + c] *= (e2 / sm2);               // zm
    }
    __syncthreads();
    for (int q = tid; q < 32*32; q += 256){
        int w = q >> 5, c4 = (q & 31) * 4;
        size_t o = (size_t)(r0 + w)*128 + c4;
        store_hl(g_zhh, g_zhl, o, *(float4*)&s_vh[w*AT_P + c4]);
        store_hl(g_zmh, g_zml, o, *(float4*)&s_vm[w*AT_P + c4]);
    }
}

// ---------------- layout transposes ----------------------------------------
#define SMEM_TR (128*132*4)
__global__ __launch_bounds__(256) void k_xT(const float* __restrict__ x){
    extern __shared__ float s[];
    int bid = blockIdx.x;
    int b = bid >> 7, t = (bid >> 3) & 15, n0 = (bid & 7) * 128;
    const float* src = x + (size_t)(b*16 + t)*128*1024;
    for (int q = threadIdx.x; q < 128*32; q += 256){
        int c = q >> 5, n4 = (q & 31) * 4;
        float4 v = *(const float4*)(src + (size_t)c*1024 + n0 + n4);
        s[(n4+0)*132 + c] = v.x; s[(n4+1)*132 + c] = v.y;
        s[(n4+2)*132 + c] = v.z; s[(n4+3)*132 + c] = v.w;
    }
    __syncthreads();
    size_t base = ((size_t)t*NPIX + b*1024 + n0)*128;
    for (int q = threadIdx.x; q < 128*32; q += 256){
        int n = q >> 5, c4 = (q & 31) * 4;
        store_hl(g_xTh, g_xTl, base + (size_t)n*128 + c4, *(float4*)&s[n*132 + c4]);
    }
}
__global__ __launch_bounds__(256) void k_init(const float* __restrict__ c0){
    extern __shared__ float s[];
    int b = blockIdx.x >> 3, n0 = (blockIdx.x & 7) * 128;
    const float* src = c0 + (size_t)b*128*1024;
    for (int q = threadIdx.x; q < 128*32; q += 256){
        int c = q >> 5, n4 = (q & 31) * 4;
        float4 v = *(const float4*)(src + (size_t)c*1024 + n0 + n4);
        s[(n4+0)*132 + c] = v.x; s[(n4+1)*132 + c] = v.y;
        s[(n4+2)*132 + c] = v.z; s[(n4+3)*132 + c] = v.w;
    }
    __syncthreads();
    size_t base = (size_t)(b*1024 + n0)*128;
    float4 zz = {0.f,0.f,0.f,0.f};
    for (int q = threadIdx.x; q < 128*32; q += 256){
        int n = q >> 5, c4 = (q & 31) * 4;
        size_t o = base + (size_t)n*128 + c4;
        *(float4*)(g_C + o) = *(float4*)&s[n*132 + c4];
        *(float4*)(g_m + o) = zz;
        store_hl(g_Hh, g_Hl, o, zz);
        store_hl(g_mh, g_ml, o, zz);
    }
}
__global__ __launch_bounds__(256) void k_outT(float* __restrict__ out){
    extern __shared__ float s[];
    int b = blockIdx.x >> 3, n0 = (blockIdx.x & 7) * 128;
    const float* src = g_H32 + (size_t)(b*1024 + n0)*128;
    for (int q = threadIdx.x; q < 128*32; q += 256){
        int n = q >> 5, c4 = (q & 31) * 4;
        float4 v = *(const float4*)(src + (size_t)n*128 + c4);
        s[(c4+0)*132 + n] = v.x; s[(c4+1)*132 + n] = v.y;
        s[(c4+2)*132 + n] = v.z; s[(c4+3)*132 + n] = v.w;
    }
    __syncthreads();
    float* dst = out + (size_t)b*128*1024;
    for (int q = threadIdx.x; q < 128*32; q += 256){
        int c = q >> 5, n4 = (q & 31) * 4;
        *(float4*)(dst + (size_t)c*1024 + n0 + n4) = *(float4*)&s[c*132 + n4];
    }
}

// ---------------------------------------------------------------------------
extern "C" void kernel_launch(void* const* d_in, const int* in_sizes, int n_in,
                              void* d_out, int out_size)
{
    const float* x  = (const float*)d_in[0];
    const float* c0 = (const float*)d_in[1];
    const float* W5 = (const float*)d_in[2];
    const float* b5 = (const float*)d_in[3];
    const float* W8 = (const float*)d_in[4];
    const float* b8 = (const float*)d_in[5];
    float* out = (float*)d_out;

    cudaFuncSetAttribute(gemm2, cudaFuncAttributeMaxDynamicSharedMemorySize, SMEM_G2);
    cudaFuncSetAttribute(k_attn, cudaFuncAttributeMaxDynamicSharedMemorySize, SMEM_ATTN);
    cudaFuncSetAttribute(k_xT,   cudaFuncAttributeMaxDynamicSharedMemorySize, SMEM_TR);
    cudaFuncSetAttribute(k_init, cudaFuncAttributeMaxDynamicSharedMemorySize, SMEM_TR);
    cudaFuncSetAttribute(k_outT, cudaFuncAttributeMaxDynamicSharedMemorySize, SMEM_TR);

    float *pY, *pY4, *pG3;
    __half *pHh,*pHl,*pmh,*pml,*pzfh,*pzfl,*pzhh,*pzhl,*pzmh,*pzml,*pxTh,*pxTl;
    __half *pW5h,*pW5l,*pW8h,*pW8l;
    cudaGetSymbolAddress((void**)&pY,  g_Y);
    cudaGetSymbolAddress((void**)&pY4, g_y4);
    cudaGetSymbolAddress((void**)&pG3, g_g3);
    cudaGetSymbolAddress((void**)&pHh, g_Hh);  cudaGetSymbolAddress((void**)&pHl, g_Hl);
    cudaGetSymbolAddress((void**)&pmh, g_mh);  cudaGetSymbolAddress((void**)&pml, g_ml);
    cudaGetSymbolAddress((void**)&pzfh,g_zfh); cudaGetSymbolAddress((void**)&pzfl,g_zfl);
    cudaGetSymbolAddress((void**)&pzhh,g_zhh); cudaGetSymbolAddress((void**)&pzhl,g_zhl);
    cudaGetSymbolAddress((void**)&pzmh,g_zmh); cudaGetSymbolAddress((void**)&pzml,g_zml);
    cudaGetSymbolAddress((void**)&pxTh,g_xTh); cudaGetSymbolAddress((void**)&pxTl,g_xTl);
    cudaGetSymbolAddress((void**)&pW5h,g_W5h); cudaGetSymbolAddress((void**)&pW5l,g_W5l);
    cudaGetSymbolAddress((void**)&pW8h,g_W8h); cudaGetSymbolAddress((void**)&pW8l,g_W8l);

    k_wprep<<<(5*128*128 + 8*128*256 + 255)/256, 256>>>(W5, W8);
    k_xT<<<2048, 256, SMEM_TR>>>(x);
    k_init<<<128, 256, SMEM_TR>>>(c0);

    for (int t = 0; t < TT; t++){
        const size_t xo = (size_t)t*NPIX*128;
        // conv10..13 on [H | x_t], K=256 -> y4
        gemm2<<<dim3(256,4), 256, SMEM_G2>>>(pHh, pHl, pxTh + xo, pxTl + xo, 128,
            nullptr, nullptr, 4, 256,
            pW8h + (size_t)4*256*128, pW8l + (size_t)4*256*128, b8 + 4*128,
            pY4, 512, 0, nullptr, nullptr);
        k_lstm<<<2048, 256>>>();
        // conv1..3 on H, conv4..5 on m, K=128 -> Y
        gemm2<<<dim3(256,5), 256, SMEM_G2>>>(pHh, pHl, nullptr, nullptr, 128,
            pmh, pml, 3, 128,
            pW5h, pW5l, b5,
            pY, 640, 0, nullptr, nullptr);
        k_attn<<<512, 256, SMEM_ATTN>>>();
        // conv6 on [zh | zm], K=256 -> z (fp16 pair)
        gemm2<<<dim3(256,1), 256, SMEM_G2>>>(pzhh, pzhl, pzmh, pzml, 128,
            nullptr, nullptr, 9, 256,
            pW8h, pW8l, b8,
            nullptr, 0, 0, pzfh, pzfl);
        // conv7..9 on [H | z], K=256 -> g3
        gemm2<<<dim3(256,3), 256, SMEM_G2>>>(pHh, pHl, pzfh, pzfl, 128,
            nullptr, nullptr, 9, 256,
            pW8h + (size_t)1*256*128, pW8l + (size_t)1*256*128, b8 + 128,
            pG3, 384, 0, nullptr, nullptr);
        k_final<<<2048, 256>>>();
    }
    k_outT<<<128, 256, SMEM_TR>>>(out);
}